// round 6
// baseline (speedup 1.0000x reference)
#include <cuda_runtime.h>
#include <cuda_bf16.h>
#include <math.h>
#include <stdint.h>

#define NEG_SLOPE 0.2f
#define EPS_BN 1e-5f
#define N_NODES 20000
#define F_IN_D 128
#define E_EDGES 320000
#define E_TOT (E_EDGES + N_NODES)
#define HD_MAX 256
#define G_GRAPHS 64
#define OUT_DIM 128
#define NCLS_D 10

// ---------------- scratch ----------------
__device__ float g_h[N_NODES * HD_MAX];
__device__ float g_o[N_NODES * HD_MAX];
__device__ float g_es[N_NODES * 4];
__device__ float g_ed[N_NODES * 4];
__device__ int   g_deg[N_NODES];
__device__ int   g_rowptr[N_NODES + 1];
__device__ int   g_cursor[N_NODES];
__device__ int   g_csrc[E_TOT];
__device__ float g_bnstat[3 * 2 * HD_MAX];   // [layer][sum/sq][ch]
__device__ float g_scale[HD_MAX];
__device__ float g_shift[HD_MAX];
__device__ float g_feat[G_GRAPHS * OUT_DIM];
__device__ int   g_start[G_GRAPHS + 1];

// ---------------- utility ----------------
__global__ void k_zero_i(int* p, int n) {
    int i = blockIdx.x * blockDim.x + threadIdx.x;
    if (i < n) p[i] = 0;
}
__global__ void k_zero_f(float* p, int n) {
    int i = blockIdx.x * blockDim.x + threadIdx.x;
    if (i < n) p[i] = 0.f;
}

// ---------------- CSR build ----------------
__global__ void k_deg(const int* __restrict__ ei, int E, int ET, int* __restrict__ deg) {
    int e = blockIdx.x * blockDim.x + threadIdx.x;
    if (e >= ET) return;
    int d = (e < E) ? ei[E + e] : (e - E);
    atomicAdd(&deg[d], 1);
}

__global__ void k_scan(const int* __restrict__ deg, int* __restrict__ rowptr,
                       int* __restrict__ cursor, int n) {
    __shared__ int sh[1024];
    int t = threadIdx.x;
    int items = (n + 1023) / 1024;
    int b0 = t * items;
    int loc = 0;
    for (int i = 0; i < items; i++) {
        int idx = b0 + i;
        if (idx < n) loc += deg[idx];
    }
    sh[t] = loc;
    __syncthreads();
    for (int off = 1; off < 1024; off <<= 1) {
        int v = (t >= off) ? sh[t - off] : 0;
        __syncthreads();
        sh[t] += v;
        __syncthreads();
    }
    int run = sh[t] - loc;
    for (int i = 0; i < items; i++) {
        int idx = b0 + i;
        if (idx < n) {
            rowptr[idx] = run;
            cursor[idx] = run;
            run += deg[idx];
        }
    }
    if (t == 1023) rowptr[n] = sh[1023];
}

__global__ void k_fill(const int* __restrict__ ei, int E, int ET,
                       int* __restrict__ cursor, int* __restrict__ csrc) {
    int e = blockIdx.x * blockDim.x + threadIdx.x;
    if (e >= ET) return;
    int s, d;
    if (e < E) { s = ei[e]; d = ei[E + e]; }
    else { s = e - E; d = e - E; }
    int pos = atomicAdd(&cursor[d], 1);
    csrc[pos] = s;
}

__global__ void k_ranges(const int* __restrict__ batch, int n, int* __restrict__ start) {
    int g = threadIdx.x;
    if (g > G_GRAPHS) return;
    if (g == G_GRAPHS) { start[G_GRAPHS] = n; return; }
    int lo = 0, hi = n;
    while (lo < hi) {
        int mid = (lo + hi) >> 1;
        if (batch[mid] < g) lo = mid + 1; else hi = mid;
    }
    start[g] = lo;
}

// ---------------- bf16 split helpers ----------------
__device__ __forceinline__ uint32_t pack_hi(float x0, float x1) {
    __nv_bfloat16 h0 = __float2bfloat16_rn(x0);
    __nv_bfloat16 h1 = __float2bfloat16_rn(x1);
    return (uint32_t)__bfloat16_as_ushort(h0) | ((uint32_t)__bfloat16_as_ushort(h1) << 16);
}
__device__ __forceinline__ uint32_t pack_lo(float x0, float x1) {
    __nv_bfloat16 h0 = __float2bfloat16_rn(x0);
    __nv_bfloat16 h1 = __float2bfloat16_rn(x1);
    __nv_bfloat16 l0 = __float2bfloat16_rn(x0 - __bfloat162float(h0));
    __nv_bfloat16 l1 = __float2bfloat16_rn(x1 - __bfloat162float(h1));
    return (uint32_t)__bfloat16_as_ushort(l0) | ((uint32_t)__bfloat16_as_ushort(l1) << 16);
}
__device__ __forceinline__ void mma_bf16(float* c, const uint32_t* a, uint32_t b0, uint32_t b1) {
    asm volatile(
        "mma.sync.aligned.m16n8k16.row.col.f32.bf16.bf16.f32 "
        "{%0,%1,%2,%3}, {%4,%5,%6,%7}, {%8,%9}, {%0,%1,%2,%3};"
        : "+f"(c[0]), "+f"(c[1]), "+f"(c[2]), "+f"(c[3])
        : "r"(a[0]), "r"(a[1]), "r"(a[2]), "r"(a[3]), "r"(b0), "r"(b1));
}

// ---------------- Tensor-core GEMM: bf16 2-term split, 128x128x16 steps ----------------
#define SMP2 136
template <bool FUSE>
__global__ __launch_bounds__(256, 2) void k_gemm_tc(const float* __restrict__ A,
                                                    const float* __restrict__ B,
                                                    float* __restrict__ C,
                                                    int M, int K, int Nd,
                                                    const float* __restrict__ scale,
                                                    const float* __restrict__ shift) {
    __shared__ __align__(16) uint32_t Ah[2][8][SMP2];
    __shared__ __align__(16) uint32_t Al[2][8][SMP2];
    __shared__ __align__(16) uint32_t Bh[2][8][SMP2];
    __shared__ __align__(16) uint32_t Bl[2][8][SMP2];
    __shared__ float ssc[HD_MAX], ssh[HD_MAX];
    int t = threadIdx.x;
    if (FUSE) {
        for (int i = t; i < K; i += 256) { ssc[i] = scale[i]; ssh[i] = shift[i]; }
        __syncthreads();
    }
    int bm = blockIdx.x * 128, bn = blockIdx.y * 128;
    int warp = t >> 5, lane = t & 31;
    int wm = (warp >> 2) * 64, wn = (warp & 3) * 32;
    int gid = lane >> 2, tig = lane & 3;

    int ar = t >> 1, akb = (t & 1) * 8;
    bool avalid = (bm + ar) < M;
    const float* Ap = A + (size_t)(bm + ar) * K + akb;
    int bkr = warp * 2, bcc = lane * 4;
    const float* Bp = B + (size_t)bkr * Nd + bn + bcc;

    float acc[4][4][4];
#pragma unroll
    for (int mt = 0; mt < 4; mt++)
#pragma unroll
        for (int nt = 0; nt < 4; nt++)
#pragma unroll
            for (int c = 0; c < 4; c++) acc[mt][nt][c] = 0.f;

    float4 a0, a1, b0, b1;

    auto stage = [&](int buf, int k0) {
        float v[8] = {a0.x, a0.y, a0.z, a0.w, a1.x, a1.y, a1.z, a1.w};
        if (FUSE) {
#pragma unroll
            for (int j = 0; j < 8; j++)
                v[j] = fmaxf(v[j] * ssc[k0 + akb + j] + ssh[k0 + akb + j], 0.f);
        }
#pragma unroll
        for (int j2 = 0; j2 < 4; j2++) {
            Ah[buf][(akb >> 1) + j2][ar] = pack_hi(v[2 * j2], v[2 * j2 + 1]);
            Al[buf][(akb >> 1) + j2][ar] = pack_lo(v[2 * j2], v[2 * j2 + 1]);
        }
        float r0[4] = {b0.x, b0.y, b0.z, b0.w};
        float r1[4] = {b1.x, b1.y, b1.z, b1.w};
        uint32_t wh[4], wl[4];
#pragma unroll
        for (int i = 0; i < 4; i++) {
            wh[i] = pack_hi(r0[i], r1[i]);
            wl[i] = pack_lo(r0[i], r1[i]);
        }
        *(uint4*)&Bh[buf][warp][bcc] = make_uint4(wh[0], wh[1], wh[2], wh[3]);
        *(uint4*)&Bl[buf][warp][bcc] = make_uint4(wl[0], wl[1], wl[2], wl[3]);
    };

    if (avalid) { a0 = *(const float4*)Ap; a1 = *(const float4*)(Ap + 4); }
    else { a0 = make_float4(0, 0, 0, 0); a1 = a0; }
    b0 = *(const float4*)Bp;
    b1 = *(const float4*)(Bp + Nd);
    stage(0, 0);
    __syncthreads();

    int nk = K >> 4;
    for (int kt = 0; kt < nk; kt++) {
        int buf = kt & 1;
        if (kt + 1 < nk) {
            int k0 = (kt + 1) << 4;
            if (avalid) { a0 = *(const float4*)(Ap + k0); a1 = *(const float4*)(Ap + k0 + 4); }
            else { a0 = make_float4(0, 0, 0, 0); a1 = a0; }
            b0 = *(const float4*)(Bp + (size_t)k0 * Nd);
            b1 = *(const float4*)(Bp + (size_t)(k0 + 1) * Nd);
        }

        uint32_t fbh[4][2], fbl[4][2];
#pragma unroll
        for (int nt = 0; nt < 4; nt++) {
            int c0 = wn + nt * 8 + gid;
            fbh[nt][0] = Bh[buf][tig][c0];
            fbh[nt][1] = Bh[buf][tig + 4][c0];
            fbl[nt][0] = Bl[buf][tig][c0];
            fbl[nt][1] = Bl[buf][tig + 4][c0];
        }
#pragma unroll
        for (int mt = 0; mt < 4; mt++) {
            int r0i = wm + mt * 16 + gid;
            uint32_t ah[4], al[4];
            ah[0] = Ah[buf][tig][r0i];
            ah[1] = Ah[buf][tig][r0i + 8];
            ah[2] = Ah[buf][tig + 4][r0i];
            ah[3] = Ah[buf][tig + 4][r0i + 8];
            al[0] = Al[buf][tig][r0i];
            al[1] = Al[buf][tig][r0i + 8];
            al[2] = Al[buf][tig + 4][r0i];
            al[3] = Al[buf][tig + 4][r0i + 8];
            // sweep nt per term: same-acc dependency distance = 4 MMAs
#pragma unroll
            for (int nt = 0; nt < 4; nt++)
                mma_bf16(acc[mt][nt], ah, fbh[nt][0], fbh[nt][1]);  // hi*hi
#pragma unroll
            for (int nt = 0; nt < 4; nt++)
                mma_bf16(acc[mt][nt], ah, fbl[nt][0], fbl[nt][1]);  // hi*lo
#pragma unroll
            for (int nt = 0; nt < 4; nt++)
                mma_bf16(acc[mt][nt], al, fbh[nt][0], fbh[nt][1]);  // lo*hi
        }

        if (kt + 1 < nk) {
            int k0 = (kt + 1) << 4;
            stage(buf ^ 1, k0);
        }
        __syncthreads();
    }

#pragma unroll
    for (int mt = 0; mt < 4; mt++) {
        int r0i = bm + wm + mt * 16 + gid;
        int r1i = r0i + 8;
#pragma unroll
        for (int nt = 0; nt < 4; nt++) {
            int cc = bn + wn + nt * 8 + tig * 2;
            if (r0i < M) *(float2*)&C[(size_t)r0i * Nd + cc] =
                make_float2(acc[mt][nt][0], acc[mt][nt][1]);
            if (r1i < M) *(float2*)&C[(size_t)r1i * Nd + cc] =
                make_float2(acc[mt][nt][2], acc[mt][nt][3]);
        }
    }
}

// ---------------- per-node attention src/dst scores ----------------
template <int H, int D>
__global__ void k_srcdst(const float* __restrict__ h, const float* __restrict__ asrc,
                         const float* __restrict__ adst, float* __restrict__ es,
                         float* __restrict__ ed, int n) {
    constexpr int HD = H * D, PL = HD / 32;
    int w = (blockIdx.x * blockDim.x + threadIdx.x) >> 5;
    int lane = threadIdx.x & 31;
    if (w >= n) return;
    float ps[H], pd[H];
#pragma unroll
    for (int hh = 0; hh < H; hh++) { ps[hh] = 0.f; pd[hh] = 0.f; }
#pragma unroll
    for (int k = 0; k < PL; k++) {
        int c = lane + 32 * k;
        float hv = h[(size_t)w * HD + c];
        const int hh = (32 * k) / D;
        ps[hh] += hv * asrc[c];
        pd[hh] += hv * adst[c];
    }
#pragma unroll
    for (int off = 16; off; off >>= 1) {
#pragma unroll
        for (int hh = 0; hh < H; hh++) {
            ps[hh] += __shfl_xor_sync(0xffffffffu, ps[hh], off);
            pd[hh] += __shfl_xor_sync(0xffffffffu, pd[hh], off);
        }
    }
    if (lane == 0) {
#pragma unroll
        for (int hh = 0; hh < H; hh++) {
            es[w * H + hh] = ps[hh];
            ed[w * H + hh] = pd[hh];
        }
    }
}

// ---------------- fused single-pass softmax + aggregation + BN stats ----------------
// out = (sum_p e^{e_p} h[src_p]) / sum_p e^{e_p}  (exp(e)/sum == exp(e-m)/sum, |e| small)
// Each lane sees every edge of its node, so z needs no cross-lane reduction.
template <int H, int D>
__global__ __launch_bounds__(256) void k_agg_fused(
        const float* __restrict__ h, const float* __restrict__ es,
        const float* __restrict__ ed, const int* __restrict__ rowptr,
        const int* __restrict__ csrc, const float* __restrict__ bias,
        float* __restrict__ outp, float* __restrict__ bnsum,
        float* __restrict__ bnsq, int n) {
    constexpr int HD = H * D, PL = HD / 32, NV = PL / 4;
    __shared__ float ssum[HD], ssq[HD];
    int t = threadIdx.x;
    for (int i = t; i < HD; i += 256) { ssum[i] = 0.f; ssq[i] = 0.f; }
    __syncthreads();

    int node = (blockIdx.x * 256 + t) >> 5;
    int lane = t & 31;
    const int hme = (lane * PL) / D;

    if (node < n) {
        float edme = ed[node * H + hme];
        int p0 = rowptr[node], p1 = rowptr[node + 1];
        float4 acc[NV];
#pragma unroll
        for (int q = 0; q < NV; q++) acc[q] = make_float4(0.f, 0.f, 0.f, 0.f);
        float z = 0.f;
#pragma unroll 2
        for (int p = p0; p < p1; p++) {
            int s = csrc[p];
            float e = es[s * H + hme] + edme;
            e = (e > 0.f) ? e : NEG_SLOPE * e;
            float w = __expf(e);
            z += w;
            const float4* hs = (const float4*)(h + (size_t)s * HD + lane * PL);
#pragma unroll
            for (int q = 0; q < NV; q++) {
                float4 v = hs[q];
                acc[q].x += v.x * w; acc[q].y += v.y * w;
                acc[q].z += v.z * w; acc[q].w += v.w * w;
            }
        }
        float iz = 1.f / z;
        const float4* bb = (const float4*)(bias + lane * PL);
        float4* op = (float4*)(outp + (size_t)node * HD + lane * PL);
#pragma unroll
        for (int q = 0; q < NV; q++) {
            float4 b = bb[q];
            float4 v = make_float4(acc[q].x * iz + b.x, acc[q].y * iz + b.y,
                                   acc[q].z * iz + b.z, acc[q].w * iz + b.w);
            op[q] = v;
            int c = lane * PL + q * 4;
            atomicAdd(&ssum[c + 0], v.x); atomicAdd(&ssq[c + 0], v.x * v.x);
            atomicAdd(&ssum[c + 1], v.y); atomicAdd(&ssq[c + 1], v.y * v.y);
            atomicAdd(&ssum[c + 2], v.z); atomicAdd(&ssq[c + 2], v.z * v.z);
            atomicAdd(&ssum[c + 3], v.w); atomicAdd(&ssq[c + 3], v.w * v.w);
        }
    }
    __syncthreads();
    for (int i = t; i < HD; i += 256) {
        atomicAdd(&bnsum[i], ssum[i]);
        atomicAdd(&bnsq[i], ssq[i]);
    }
}

// ---------------- BN finalize (from accumulated sums) ----------------
__global__ void k_bnfinal(const float* __restrict__ gamma, const float* __restrict__ beta,
                          int n, int C, const float* __restrict__ sum,
                          const float* __restrict__ sq, float* __restrict__ scale,
                          float* __restrict__ shift) {
    int c = threadIdx.x;
    if (c >= C) return;
    float mu = sum[c] / (float)n;
    float var = sq[c] / (float)n - mu * mu;
    float sc = gamma[c] * rsqrtf(var + EPS_BN);
    scale[c] = sc;
    shift[c] = beta[c] - mu * sc;
}

// ---------------- pooling (fused BN+ReLU of last layer) ----------------
__global__ void k_pool(const float* __restrict__ o, const int* __restrict__ start,
                       const float* __restrict__ scale, const float* __restrict__ shift,
                       float* __restrict__ feat) {
    __shared__ float sm[4][OUT_DIM];
    int g = blockIdx.x;
    int part = blockIdx.y;
    int c = threadIdx.x & 127;
    int rgrp = threadIdx.x >> 7;
    int s0 = start[g], s1 = start[g + 1];
    int len = s1 - s0;
    int chunk = (len + 3) >> 2;
    int r0 = s0 + part * chunk;
    int r1 = min(s1, r0 + chunk);
    float sc = scale[c], sh = shift[c];
    float sum = 0.f;
    for (int r = r0 + rgrp; r < r1; r += 4) {
        float v = o[(size_t)r * OUT_DIM + c];
        sum += fmaxf(v * sc + sh, 0.f);
    }
    sm[rgrp][c] = sum;
    __syncthreads();
    if (threadIdx.x < OUT_DIM) {
        float s = sm[0][c] + sm[1][c] + sm[2][c] + sm[3][c];
        atomicAdd(&feat[g * OUT_DIM + c], s);
    }
}

// ---------------- heads ----------------
__global__ void k_heads(const float* __restrict__ featsum, const int* __restrict__ start,
                        const float* __restrict__ clfW, const float* __restrict__ clfb,
                        const float* __restrict__ dW1, const float* __restrict__ db1,
                        const float* __restrict__ dW2, const float* __restrict__ db2,
                        float* __restrict__ out) {
    __shared__ float f[OUT_DIM];
    __shared__ float dh[64];
    int g = blockIdx.x, t = threadIdx.x;
    float c = (float)max(start[g + 1] - start[g], 1);
    f[t] = featsum[g * OUT_DIM + t] / c;
    out[G_GRAPHS * NCLS_D + G_GRAPHS * 2 + g * OUT_DIM + t] = f[t];
    __syncthreads();
    if (t < 64) {
        float s = db1[t];
        for (int k = 0; k < OUT_DIM; k++) s += f[k] * dW1[k * 64 + t];
        dh[t] = fmaxf(s, 0.f);
    }
    if (t < NCLS_D) {
        float s = clfb[t];
        for (int k = 0; k < OUT_DIM; k++) s += f[k] * clfW[k * NCLS_D + t];
        out[g * NCLS_D + t] = s;
    }
    __syncthreads();
    if (t < 2) {
        float s = db2[t];
        for (int k = 0; k < 64; k++) s += dh[k] * dW2[k * 2 + t];
        out[G_GRAPHS * NCLS_D + g * 2 + t] = s;
    }
}

// ---------------- launch ----------------
static inline int cdiv(int a, int b) { return (a + b - 1) / b; }

extern "C" void kernel_launch(void* const* d_in, const int* in_sizes, int n_in,
                              void* d_out, int out_size) {
    const float* x = (const float*)d_in[0];
    const int* ei = (const int*)d_in[1];
    const int* batch = (const int*)d_in[2];
    const float* W[3]   = {(const float*)d_in[3],  (const float*)d_in[9],  (const float*)d_in[15]};
    const float* Asr[3] = {(const float*)d_in[4],  (const float*)d_in[10], (const float*)d_in[16]};
    const float* Ads[3] = {(const float*)d_in[5],  (const float*)d_in[11], (const float*)d_in[17]};
    const float* Bi[3]  = {(const float*)d_in[6],  (const float*)d_in[12], (const float*)d_in[18]};
    const float* Ga[3]  = {(const float*)d_in[7],  (const float*)d_in[13], (const float*)d_in[19]};
    const float* Be[3]  = {(const float*)d_in[8],  (const float*)d_in[14], (const float*)d_in[20]};
    const float* clfW = (const float*)d_in[21];
    const float* clfb = (const float*)d_in[22];
    const float* dW1 = (const float*)d_in[23];
    const float* db1 = (const float*)d_in[24];
    const float* dW2 = (const float*)d_in[25];
    const float* db2 = (const float*)d_in[26];

    int N = in_sizes[0] / F_IN_D;
    int E = in_sizes[1] / 2;
    int ET = E + N;

    float *p_h, *p_o, *p_es, *p_ed, *p_stat, *p_scale, *p_shift, *p_feat;
    int *p_deg, *p_rowptr, *p_cursor, *p_csrc, *p_start;
    cudaGetSymbolAddress((void**)&p_h, g_h);
    cudaGetSymbolAddress((void**)&p_o, g_o);
    cudaGetSymbolAddress((void**)&p_es, g_es);
    cudaGetSymbolAddress((void**)&p_ed, g_ed);
    cudaGetSymbolAddress((void**)&p_deg, g_deg);
    cudaGetSymbolAddress((void**)&p_rowptr, g_rowptr);
    cudaGetSymbolAddress((void**)&p_cursor, g_cursor);
    cudaGetSymbolAddress((void**)&p_csrc, g_csrc);
    cudaGetSymbolAddress((void**)&p_stat, g_bnstat);
    cudaGetSymbolAddress((void**)&p_scale, g_scale);
    cudaGetSymbolAddress((void**)&p_shift, g_shift);
    cudaGetSymbolAddress((void**)&p_feat, g_feat);
    cudaGetSymbolAddress((void**)&p_start, g_start);

    const int Kd[3] = {F_IN_D, 256, 256};
    const int Hh[3] = {4, 4, 1};

    // GEMM layer0 at launch index 3 so the ncu window lands on it.
    k_zero_i<<<cdiv(N, 256), 256>>>(p_deg, N);
    k_deg<<<cdiv(ET, 256), 256>>>(ei, E, ET, p_deg);
    k_scan<<<1, 1024>>>(p_deg, p_rowptr, p_cursor, N);
    {
        dim3 gg(cdiv(N, 128), 2);
        k_gemm_tc<false><<<gg, 256>>>(x, W[0], p_h, N, Kd[0], 256, nullptr, nullptr);
    }
    k_fill<<<cdiv(ET, 256), 256>>>(ei, E, ET, p_cursor, p_csrc);
    k_ranges<<<1, 128>>>(batch, N, p_start);
    k_zero_f<<<cdiv(3 * 2 * HD_MAX + G_GRAPHS * OUT_DIM, 256), 256>>>(p_stat,
        3 * 2 * HD_MAX);  // stats; feat zeroed separately below

    for (int li = 0; li < 3; li++) {
        int HD = (li < 2) ? 256 : 128;
        float* bnsum = p_stat + li * 2 * HD_MAX;
        float* bnsq = bnsum + HD_MAX;
        if (li > 0) {
            dim3 gg(cdiv(N, 128), HD / 128);
            k_gemm_tc<true><<<gg, 256>>>(p_o, W[li], p_h, N, Kd[li], HD, p_scale, p_shift);
        }

        int aggBlocks = cdiv(N * 32, 256);
        if (Hh[li] == 4) {
            k_srcdst<4, 64><<<aggBlocks, 256>>>(p_h, Asr[li], Ads[li], p_es, p_ed, N);
            k_agg_fused<4, 64><<<aggBlocks, 256>>>(p_h, p_es, p_ed, p_rowptr, p_csrc,
                                                   Bi[li], p_o, bnsum, bnsq, N);
        } else {
            k_srcdst<1, 128><<<aggBlocks, 256>>>(p_h, Asr[li], Ads[li], p_es, p_ed, N);
            k_agg_fused<1, 128><<<aggBlocks, 256>>>(p_h, p_es, p_ed, p_rowptr, p_csrc,
                                                    Bi[li], p_o, bnsum, bnsq, N);
        }

        k_bnfinal<<<1, HD>>>(Ga[li], Be[li], N, HD, bnsum, bnsq, p_scale, p_shift);
    }

    // --- pooling + heads ---
    k_zero_f<<<cdiv(G_GRAPHS * OUT_DIM, 256), 256>>>(p_feat, G_GRAPHS * OUT_DIM);
    {
        dim3 pg(G_GRAPHS, 4);
        k_pool<<<pg, 512>>>(p_o, p_start, p_scale, p_shift, p_feat);
    }
    k_heads<<<G_GRAPHS, 128>>>(p_feat, p_start, clfW, clfb, dW1, db1, dW2, db2,
                               (float*)d_out);
}

// round 7
// speedup vs baseline: 1.1506x; 1.1506x over previous
#include <cuda_runtime.h>
#include <cuda_bf16.h>
#include <math.h>
#include <stdint.h>

#define NEG_SLOPE 0.2f
#define EPS_BN 1e-5f
#define N_NODES 20000
#define F_IN_D 128
#define E_EDGES 320000
#define E_TOT (E_EDGES + N_NODES)
#define HD_MAX 256
#define G_GRAPHS 64
#define OUT_DIM 128
#define NCLS_D 10
#define NSTAT_BLK 160

// ---------------- scratch ----------------
__device__ float g_h[N_NODES * HD_MAX];
__device__ float g_o[N_NODES * HD_MAX];
__device__ float g_es[N_NODES * 4];
__device__ float g_ed[N_NODES * 4];
__device__ int   g_deg[N_NODES];
__device__ int   g_rowptr[N_NODES + 1];
__device__ int   g_cursor[N_NODES];
__device__ int   g_csrc[E_TOT];
__device__ float g_bnpart[NSTAT_BLK * 2 * HD_MAX];
__device__ float g_scale[HD_MAX];
__device__ float g_shift[HD_MAX];
__device__ float g_feat[G_GRAPHS * OUT_DIM];
__device__ int   g_start[G_GRAPHS + 1];

// ---------------- utility ----------------
__global__ void k_zero_i(int* p, int n) {
    int i = blockIdx.x * blockDim.x + threadIdx.x;
    if (i < n) p[i] = 0;
}
__global__ void k_zero_f(float* p, int n) {
    int i = blockIdx.x * blockDim.x + threadIdx.x;
    if (i < n) p[i] = 0.f;
}

// ---------------- CSR build ----------------
__global__ void k_deg(const int* __restrict__ ei, int E, int ET, int* __restrict__ deg) {
    int e = blockIdx.x * blockDim.x + threadIdx.x;
    if (e >= ET) return;
    int d = (e < E) ? ei[E + e] : (e - E);
    atomicAdd(&deg[d], 1);
}

__global__ void k_scan(const int* __restrict__ deg, int* __restrict__ rowptr,
                       int* __restrict__ cursor, int n) {
    __shared__ int sh[1024];
    int t = threadIdx.x;
    int items = (n + 1023) / 1024;
    int b0 = t * items;
    int loc = 0;
    for (int i = 0; i < items; i++) {
        int idx = b0 + i;
        if (idx < n) loc += deg[idx];
    }
    sh[t] = loc;
    __syncthreads();
    for (int off = 1; off < 1024; off <<= 1) {
        int v = (t >= off) ? sh[t - off] : 0;
        __syncthreads();
        sh[t] += v;
        __syncthreads();
    }
    int run = sh[t] - loc;
    for (int i = 0; i < items; i++) {
        int idx = b0 + i;
        if (idx < n) {
            rowptr[idx] = run;
            cursor[idx] = run;
            run += deg[idx];
        }
    }
    if (t == 1023) rowptr[n] = sh[1023];
}

__global__ void k_fill(const int* __restrict__ ei, int E, int ET,
                       int* __restrict__ cursor, int* __restrict__ csrc) {
    int e = blockIdx.x * blockDim.x + threadIdx.x;
    if (e >= ET) return;
    int s, d;
    if (e < E) { s = ei[e]; d = ei[E + e]; }
    else { s = e - E; d = e - E; }
    int pos = atomicAdd(&cursor[d], 1);
    csrc[pos] = s;
}

__global__ void k_ranges(const int* __restrict__ batch, int n, int* __restrict__ start) {
    int g = threadIdx.x;
    if (g > G_GRAPHS) return;
    if (g == G_GRAPHS) { start[G_GRAPHS] = n; return; }
    int lo = 0, hi = n;
    while (lo < hi) {
        int mid = (lo + hi) >> 1;
        if (batch[mid] < g) lo = mid + 1; else hi = mid;
    }
    start[g] = lo;
}

// ---------------- bf16 split helpers ----------------
__device__ __forceinline__ uint32_t pack_hi(float x0, float x1) {
    __nv_bfloat16 h0 = __float2bfloat16_rn(x0);
    __nv_bfloat16 h1 = __float2bfloat16_rn(x1);
    return (uint32_t)__bfloat16_as_ushort(h0) | ((uint32_t)__bfloat16_as_ushort(h1) << 16);
}
__device__ __forceinline__ uint32_t pack_lo(float x0, float x1) {
    __nv_bfloat16 h0 = __float2bfloat16_rn(x0);
    __nv_bfloat16 h1 = __float2bfloat16_rn(x1);
    __nv_bfloat16 l0 = __float2bfloat16_rn(x0 - __bfloat162float(h0));
    __nv_bfloat16 l1 = __float2bfloat16_rn(x1 - __bfloat162float(h1));
    return (uint32_t)__bfloat16_as_ushort(l0) | ((uint32_t)__bfloat16_as_ushort(l1) << 16);
}
__device__ __forceinline__ void mma_bf16(float* c, const uint32_t* a, uint32_t b0, uint32_t b1) {
    asm volatile(
        "mma.sync.aligned.m16n8k16.row.col.f32.bf16.bf16.f32 "
        "{%0,%1,%2,%3}, {%4,%5,%6,%7}, {%8,%9}, {%0,%1,%2,%3};"
        : "+f"(c[0]), "+f"(c[1]), "+f"(c[2]), "+f"(c[3])
        : "r"(a[0]), "r"(a[1]), "r"(a[2]), "r"(a[3]), "r"(b0), "r"(b1));
}

// ---------------- Tensor-core GEMM: bf16 2-term split, 128x128x16 steps ----------------
#define SMP2 136
template <bool FUSE>
__global__ __launch_bounds__(256, 2) void k_gemm_tc(const float* __restrict__ A,
                                                    const float* __restrict__ B,
                                                    float* __restrict__ C,
                                                    int M, int K, int Nd,
                                                    const float* __restrict__ scale,
                                                    const float* __restrict__ shift) {
    __shared__ __align__(16) uint32_t Ah[2][8][SMP2];
    __shared__ __align__(16) uint32_t Al[2][8][SMP2];
    __shared__ __align__(16) uint32_t Bh[2][8][SMP2];
    __shared__ __align__(16) uint32_t Bl[2][8][SMP2];
    __shared__ float ssc[HD_MAX], ssh[HD_MAX];
    int t = threadIdx.x;
    if (FUSE) {
        for (int i = t; i < K; i += 256) { ssc[i] = scale[i]; ssh[i] = shift[i]; }
        __syncthreads();
    }
    int bm = blockIdx.x * 128, bn = blockIdx.y * 128;
    int warp = t >> 5, lane = t & 31;
    int wm = (warp >> 2) * 64, wn = (warp & 3) * 32;
    int gid = lane >> 2, tig = lane & 3;

    int ar = t >> 1, akb = (t & 1) * 8;
    bool avalid = (bm + ar) < M;
    const float* Ap = A + (size_t)(bm + ar) * K + akb;
    int bkr = warp * 2, bcc = lane * 4;
    const float* Bp = B + (size_t)bkr * Nd + bn + bcc;

    float acc[4][4][4];
#pragma unroll
    for (int mt = 0; mt < 4; mt++)
#pragma unroll
        for (int nt = 0; nt < 4; nt++)
#pragma unroll
            for (int c = 0; c < 4; c++) acc[mt][nt][c] = 0.f;

    float4 a0, a1, b0, b1;

    auto stage = [&](int buf, int k0) {
        float v[8] = {a0.x, a0.y, a0.z, a0.w, a1.x, a1.y, a1.z, a1.w};
        if (FUSE) {
#pragma unroll
            for (int j = 0; j < 8; j++)
                v[j] = fmaxf(v[j] * ssc[k0 + akb + j] + ssh[k0 + akb + j], 0.f);
        }
#pragma unroll
        for (int j2 = 0; j2 < 4; j2++) {
            Ah[buf][(akb >> 1) + j2][ar] = pack_hi(v[2 * j2], v[2 * j2 + 1]);
            Al[buf][(akb >> 1) + j2][ar] = pack_lo(v[2 * j2], v[2 * j2 + 1]);
        }
        float r0[4] = {b0.x, b0.y, b0.z, b0.w};
        float r1[4] = {b1.x, b1.y, b1.z, b1.w};
        uint32_t wh[4], wl[4];
#pragma unroll
        for (int i = 0; i < 4; i++) {
            wh[i] = pack_hi(r0[i], r1[i]);
            wl[i] = pack_lo(r0[i], r1[i]);
        }
        *(uint4*)&Bh[buf][warp][bcc] = make_uint4(wh[0], wh[1], wh[2], wh[3]);
        *(uint4*)&Bl[buf][warp][bcc] = make_uint4(wl[0], wl[1], wl[2], wl[3]);
    };

    if (avalid) { a0 = *(const float4*)Ap; a1 = *(const float4*)(Ap + 4); }
    else { a0 = make_float4(0, 0, 0, 0); a1 = a0; }
    b0 = *(const float4*)Bp;
    b1 = *(const float4*)(Bp + Nd);
    stage(0, 0);
    __syncthreads();

    int nk = K >> 4;
    for (int kt = 0; kt < nk; kt++) {
        int buf = kt & 1;
        if (kt + 1 < nk) {
            int k0 = (kt + 1) << 4;
            if (avalid) { a0 = *(const float4*)(Ap + k0); a1 = *(const float4*)(Ap + k0 + 4); }
            else { a0 = make_float4(0, 0, 0, 0); a1 = a0; }
            b0 = *(const float4*)(Bp + (size_t)k0 * Nd);
            b1 = *(const float4*)(Bp + (size_t)(k0 + 1) * Nd);
        }

        uint32_t fbh[4][2], fbl[4][2];
#pragma unroll
        for (int nt = 0; nt < 4; nt++) {
            int c0 = wn + nt * 8 + gid;
            fbh[nt][0] = Bh[buf][tig][c0];
            fbh[nt][1] = Bh[buf][tig + 4][c0];
            fbl[nt][0] = Bl[buf][tig][c0];
            fbl[nt][1] = Bl[buf][tig + 4][c0];
        }
#pragma unroll
        for (int mt = 0; mt < 4; mt++) {
            int r0i = wm + mt * 16 + gid;
            uint32_t ah[4], al[4];
            ah[0] = Ah[buf][tig][r0i];
            ah[1] = Ah[buf][tig][r0i + 8];
            ah[2] = Ah[buf][tig + 4][r0i];
            ah[3] = Ah[buf][tig + 4][r0i + 8];
            al[0] = Al[buf][tig][r0i];
            al[1] = Al[buf][tig][r0i + 8];
            al[2] = Al[buf][tig + 4][r0i];
            al[3] = Al[buf][tig + 4][r0i + 8];
#pragma unroll
            for (int nt = 0; nt < 4; nt++)
                mma_bf16(acc[mt][nt], ah, fbh[nt][0], fbh[nt][1]);  // hi*hi
#pragma unroll
            for (int nt = 0; nt < 4; nt++)
                mma_bf16(acc[mt][nt], ah, fbl[nt][0], fbl[nt][1]);  // hi*lo
#pragma unroll
            for (int nt = 0; nt < 4; nt++)
                mma_bf16(acc[mt][nt], al, fbh[nt][0], fbh[nt][1]);  // lo*hi
        }

        if (kt + 1 < nk) {
            int k0 = (kt + 1) << 4;
            stage(buf ^ 1, k0);
        }
        __syncthreads();
    }

#pragma unroll
    for (int mt = 0; mt < 4; mt++) {
        int r0i = bm + wm + mt * 16 + gid;
        int r1i = r0i + 8;
#pragma unroll
        for (int nt = 0; nt < 4; nt++) {
            int cc = bn + wn + nt * 8 + tig * 2;
            if (r0i < M) *(float2*)&C[(size_t)r0i * Nd + cc] =
                make_float2(acc[mt][nt][0], acc[mt][nt][1]);
            if (r1i < M) *(float2*)&C[(size_t)r1i * Nd + cc] =
                make_float2(acc[mt][nt][2], acc[mt][nt][3]);
        }
    }
}

// ---------------- per-node attention src/dst scores ----------------
template <int H, int D>
__global__ void k_srcdst(const float* __restrict__ h, const float* __restrict__ asrc,
                         const float* __restrict__ adst, float* __restrict__ es,
                         float* __restrict__ ed, int n) {
    constexpr int HD = H * D, PL = HD / 32;
    int w = (blockIdx.x * blockDim.x + threadIdx.x) >> 5;
    int lane = threadIdx.x & 31;
    if (w >= n) return;
    float ps[H], pd[H];
#pragma unroll
    for (int hh = 0; hh < H; hh++) { ps[hh] = 0.f; pd[hh] = 0.f; }
#pragma unroll
    for (int k = 0; k < PL; k++) {
        int c = lane + 32 * k;
        float hv = h[(size_t)w * HD + c];
        const int hh = (32 * k) / D;
        ps[hh] += hv * asrc[c];
        pd[hh] += hv * adst[c];
    }
#pragma unroll
    for (int off = 16; off; off >>= 1) {
#pragma unroll
        for (int hh = 0; hh < H; hh++) {
            ps[hh] += __shfl_xor_sync(0xffffffffu, ps[hh], off);
            pd[hh] += __shfl_xor_sync(0xffffffffu, pd[hh], off);
        }
    }
    if (lane == 0) {
#pragma unroll
        for (int hh = 0; hh < H; hh++) {
            es[w * H + hh] = ps[hh];
            ed[w * H + hh] = pd[hh];
        }
    }
}

// ---------------- single-pass softmax + aggregation (no wbuf, no smem atomics) --------
// out = (sum_p e^{e_p} h[src_p]) / sum_p e^{e_p}
template <int H, int D>
__global__ __launch_bounds__(256) void k_agg_fused(
        const float* __restrict__ h, const float* __restrict__ es,
        const float* __restrict__ ed, const int* __restrict__ rowptr,
        const int* __restrict__ csrc, const float* __restrict__ bias,
        float* __restrict__ outp, int n) {
    constexpr int HD = H * D, PL = HD / 32, NV = PL / 4;
    int node = (blockIdx.x * blockDim.x + threadIdx.x) >> 5;
    int lane = threadIdx.x & 31;
    if (node >= n) return;
    const int hme = (lane * PL) / D;

    float edme = ed[node * H + hme];
    int p0 = rowptr[node], p1 = rowptr[node + 1];
    float4 acc[NV];
#pragma unroll
    for (int q = 0; q < NV; q++) acc[q] = make_float4(0.f, 0.f, 0.f, 0.f);
    float z = 0.f;
#pragma unroll 2
    for (int p = p0; p < p1; p++) {
        int s = csrc[p];
        float e = es[s * H + hme] + edme;
        e = (e > 0.f) ? e : NEG_SLOPE * e;
        float w = __expf(e);
        z += w;
        const float4* hs = (const float4*)(h + (size_t)s * HD + lane * PL);
#pragma unroll
        for (int q = 0; q < NV; q++) {
            float4 v = hs[q];
            acc[q].x += v.x * w; acc[q].y += v.y * w;
            acc[q].z += v.z * w; acc[q].w += v.w * w;
        }
    }
    float iz = 1.f / z;
    const float4* bb = (const float4*)(bias + lane * PL);
    float4* op = (float4*)(outp + (size_t)node * HD + lane * PL);
#pragma unroll
    for (int q = 0; q < NV; q++) {
        float4 b = bb[q];
        op[q] = make_float4(acc[q].x * iz + b.x, acc[q].y * iz + b.y,
                            acc[q].z * iz + b.z, acc[q].w * iz + b.w);
    }
}

// ---------------- BN stats: per-block partials (no atomics) ----------------
__global__ void k_bnstats(const float* __restrict__ x, int n, int C,
                          float* __restrict__ part) {
    int c = threadIdx.x;
    int chunk = (n + gridDim.x - 1) / gridDim.x;
    int r0 = blockIdx.x * chunk;
    int r1 = min(n, r0 + chunk);
    float s = 0.f, q = 0.f;
    int r = r0;
    for (; r + 3 < r1; r += 4) {
        float v0 = x[(size_t)r * C + c];
        float v1 = x[(size_t)(r + 1) * C + c];
        float v2 = x[(size_t)(r + 2) * C + c];
        float v3 = x[(size_t)(r + 3) * C + c];
        s += v0 + v1 + v2 + v3;
        q += v0 * v0 + v1 * v1 + v2 * v2 + v3 * v3;
    }
    for (; r < r1; r++) {
        float v = x[(size_t)r * C + c];
        s += v; q += v * v;
    }
    part[(size_t)blockIdx.x * 2 * C + c] = s;
    part[(size_t)blockIdx.x * 2 * C + C + c] = q;
}

__global__ void k_bnfinal(const float* __restrict__ gamma, const float* __restrict__ beta,
                          int n, int C, const float* __restrict__ part,
                          float* __restrict__ scale, float* __restrict__ shift) {
    int c = threadIdx.x;
    if (c >= C) return;
    float s = 0.f, q = 0.f;
    for (int b = 0; b < NSTAT_BLK; b++) {
        s += part[(size_t)b * 2 * C + c];
        q += part[(size_t)b * 2 * C + C + c];
    }
    float mu = s / (float)n;
    float var = q / (float)n - mu * mu;
    float sc = gamma[c] * rsqrtf(var + EPS_BN);
    scale[c] = sc;
    shift[c] = beta[c] - mu * sc;
}

// ---------------- pooling (fused BN+ReLU of last layer) ----------------
__global__ void k_pool(const float* __restrict__ o, const int* __restrict__ start,
                       const float* __restrict__ scale, const float* __restrict__ shift,
                       float* __restrict__ feat) {
    __shared__ float sm[4][OUT_DIM];
    int g = blockIdx.x;
    int part = blockIdx.y;
    int c = threadIdx.x & 127;
    int rgrp = threadIdx.x >> 7;
    int s0 = start[g], s1 = start[g + 1];
    int len = s1 - s0;
    int chunk = (len + 3) >> 2;
    int r0 = s0 + part * chunk;
    int r1 = min(s1, r0 + chunk);
    float sc = scale[c], sh = shift[c];
    float sum = 0.f;
    for (int r = r0 + rgrp; r < r1; r += 4) {
        float v = o[(size_t)r * OUT_DIM + c];
        sum += fmaxf(v * sc + sh, 0.f);
    }
    sm[rgrp][c] = sum;
    __syncthreads();
    if (threadIdx.x < OUT_DIM) {
        float s = sm[0][c] + sm[1][c] + sm[2][c] + sm[3][c];
        atomicAdd(&feat[g * OUT_DIM + c], s);
    }
}

// ---------------- heads ----------------
__global__ void k_heads(const float* __restrict__ featsum, const int* __restrict__ start,
                        const float* __restrict__ clfW, const float* __restrict__ clfb,
                        const float* __restrict__ dW1, const float* __restrict__ db1,
                        const float* __restrict__ dW2, const float* __restrict__ db2,
                        float* __restrict__ out) {
    __shared__ float f[OUT_DIM];
    __shared__ float dh[64];
    int g = blockIdx.x, t = threadIdx.x;
    float c = (float)max(start[g + 1] - start[g], 1);
    f[t] = featsum[g * OUT_DIM + t] / c;
    out[G_GRAPHS * NCLS_D + G_GRAPHS * 2 + g * OUT_DIM + t] = f[t];
    __syncthreads();
    if (t < 64) {
        float s = db1[t];
        for (int k = 0; k < OUT_DIM; k++) s += f[k] * dW1[k * 64 + t];
        dh[t] = fmaxf(s, 0.f);
    }
    if (t < NCLS_D) {
        float s = clfb[t];
        for (int k = 0; k < OUT_DIM; k++) s += f[k] * clfW[k * NCLS_D + t];
        out[g * NCLS_D + t] = s;
    }
    __syncthreads();
    if (t < 2) {
        float s = db2[t];
        for (int k = 0; k < 64; k++) s += dh[k] * dW2[k * 2 + t];
        out[G_GRAPHS * NCLS_D + g * 2 + t] = s;
    }
}

// ---------------- launch ----------------
static inline int cdiv(int a, int b) { return (a + b - 1) / b; }

extern "C" void kernel_launch(void* const* d_in, const int* in_sizes, int n_in,
                              void* d_out, int out_size) {
    const float* x = (const float*)d_in[0];
    const int* ei = (const int*)d_in[1];
    const int* batch = (const int*)d_in[2];
    const float* W[3]   = {(const float*)d_in[3],  (const float*)d_in[9],  (const float*)d_in[15]};
    const float* Asr[3] = {(const float*)d_in[4],  (const float*)d_in[10], (const float*)d_in[16]};
    const float* Ads[3] = {(const float*)d_in[5],  (const float*)d_in[11], (const float*)d_in[17]};
    const float* Bi[3]  = {(const float*)d_in[6],  (const float*)d_in[12], (const float*)d_in[18]};
    const float* Ga[3]  = {(const float*)d_in[7],  (const float*)d_in[13], (const float*)d_in[19]};
    const float* Be[3]  = {(const float*)d_in[8],  (const float*)d_in[14], (const float*)d_in[20]};
    const float* clfW = (const float*)d_in[21];
    const float* clfb = (const float*)d_in[22];
    const float* dW1 = (const float*)d_in[23];
    const float* db1 = (const float*)d_in[24];
    const float* dW2 = (const float*)d_in[25];
    const float* db2 = (const float*)d_in[26];

    int N = in_sizes[0] / F_IN_D;
    int E = in_sizes[1] / 2;
    int ET = E + N;

    float *p_h, *p_o, *p_es, *p_ed, *p_part, *p_scale, *p_shift, *p_feat;
    int *p_deg, *p_rowptr, *p_cursor, *p_csrc, *p_start;
    cudaGetSymbolAddress((void**)&p_h, g_h);
    cudaGetSymbolAddress((void**)&p_o, g_o);
    cudaGetSymbolAddress((void**)&p_es, g_es);
    cudaGetSymbolAddress((void**)&p_ed, g_ed);
    cudaGetSymbolAddress((void**)&p_deg, g_deg);
    cudaGetSymbolAddress((void**)&p_rowptr, g_rowptr);
    cudaGetSymbolAddress((void**)&p_cursor, g_cursor);
    cudaGetSymbolAddress((void**)&p_csrc, g_csrc);
    cudaGetSymbolAddress((void**)&p_part, g_bnpart);
    cudaGetSymbolAddress((void**)&p_scale, g_scale);
    cudaGetSymbolAddress((void**)&p_shift, g_shift);
    cudaGetSymbolAddress((void**)&p_feat, g_feat);
    cudaGetSymbolAddress((void**)&p_start, g_start);

    const int Kd[3] = {F_IN_D, 256, 256};
    const int Hh[3] = {4, 4, 1};

    // GEMM layer0 at launch index 3 so the ncu window lands on it.
    k_zero_i<<<cdiv(N, 256), 256>>>(p_deg, N);
    k_deg<<<cdiv(ET, 256), 256>>>(ei, E, ET, p_deg);
    k_scan<<<1, 1024>>>(p_deg, p_rowptr, p_cursor, N);
    {
        dim3 gg(cdiv(N, 128), 2);
        k_gemm_tc<false><<<gg, 256>>>(x, W[0], p_h, N, Kd[0], 256, nullptr, nullptr);
    }
    k_fill<<<cdiv(ET, 256), 256>>>(ei, E, ET, p_cursor, p_csrc);
    k_ranges<<<1, 128>>>(batch, N, p_start);

    for (int li = 0; li < 3; li++) {
        int HD = (li < 2) ? 256 : 128;
        if (li > 0) {
            dim3 gg(cdiv(N, 128), HD / 128);
            k_gemm_tc<true><<<gg, 256>>>(p_o, W[li], p_h, N, Kd[li], HD, p_scale, p_shift);
        }

        int aggBlocks = cdiv(N * 32, 256);
        if (Hh[li] == 4) {
            k_srcdst<4, 64><<<aggBlocks, 256>>>(p_h, Asr[li], Ads[li], p_es, p_ed, N);
            k_agg_fused<4, 64><<<aggBlocks, 256>>>(p_h, p_es, p_ed, p_rowptr, p_csrc,
                                                   Bi[li], p_o, N);
        } else {
            k_srcdst<1, 128><<<aggBlocks, 256>>>(p_h, Asr[li], Ads[li], p_es, p_ed, N);
            k_agg_fused<1, 128><<<aggBlocks, 256>>>(p_h, p_es, p_ed, p_rowptr, p_csrc,
                                                    Bi[li], p_o, N);
        }

        k_bnstats<<<NSTAT_BLK, HD>>>(p_o, N, HD, p_part);
        k_bnfinal<<<1, HD>>>(Ga[li], Be[li], N, HD, p_part, p_scale, p_shift);
    }

    // --- pooling + heads ---
    k_zero_f<<<cdiv(G_GRAPHS * OUT_DIM, 256), 256>>>(p_feat, G_GRAPHS * OUT_DIM);
    {
        dim3 pg(G_GRAPHS, 4);
        k_pool<<<pg, 512>>>(p_o, p_start, p_scale, p_shift, p_feat);
    }
    k_heads<<<G_GRAPHS, 128>>>(p_feat, p_start, clfW, clfb, dW1, db1, dW2, db2,
                               (float*)d_out);
}